// round 8
// baseline (speedup 1.0000x reference)
#include <cuda_runtime.h>
#include <cstdint>

// Blocked online logistic-SGD scan, mbarrier-pipelined cluster version.
// Phase 1 (grid): band Gram pre-scaled by ETA/4:
//   g_WB[m][j][r] = 0.25*ETA*<x_{32m+r}, x_{32(m-1)+j}>, j in [0,64)
// Phase 2 (4-CTA cluster):
//   chain (CTA0 warp0): per segment s, h_k = half-pred; per-step critical path
//     tanh -> shfl(t) -> fma (46 cyc). Broadcasts c = 0.5*ETA*(1-t) to all CTAs.
//   workers (warps 1-8, all CTAs): apply rank-32 theta update, matvec next d,
//     DSMEM-push partials to CTA0. mbarrier handoff, no cluster barrier in loop.

#define DDIM 2048
#define NSTEPS 16384
#define BLK 32
#define NBLK (NSTEPS / BLK)   // 512
#define ETA 0.01f
#define NC 4
#define SLICE (DDIM / NC)     // 512
#define NTH 288

__device__ float g_WB[(size_t)NBLK * 64 * BLK];   // 4 MB scratch

__device__ __forceinline__ float fast_tanh(float x) {
    float r; asm("tanh.approx.f32 %0, %1;" : "=f"(r) : "f"(x)); return r;
}
__device__ __forceinline__ uint32_t smem_u32(const void* p) {
    return (uint32_t)__cvta_generic_to_shared(p);
}
__device__ __forceinline__ uint32_t mapa_rk(uint32_t a, uint32_t rk) {
    uint32_t r; asm("mapa.shared::cluster.u32 %0, %1, %2;" : "=r"(r) : "r"(a), "r"(rk));
    return r;
}
__device__ __forceinline__ void st_cluster_f32(uint32_t a, float v) {
    asm volatile("st.shared::cluster.f32 [%0], %1;" :: "r"(a), "f"(v) : "memory");
}
__device__ __forceinline__ void cluster_sync_() {
    asm volatile("barrier.cluster.arrive.aligned;" ::: "memory");
    asm volatile("barrier.cluster.wait.aligned;" ::: "memory");
}
__device__ __forceinline__ void mbar_init(uint32_t a, uint32_t cnt) {
    asm volatile("mbarrier.init.shared.b64 [%0], %1;" :: "r"(a), "r"(cnt) : "memory");
}
// remote (cluster-addressed) release-arrive
__device__ __forceinline__ void mbar_arrive_rel(uint32_t a) {
    asm volatile("mbarrier.arrive.release.cluster.shared::cluster.b64 _, [%0];"
                 :: "r"(a) : "memory");
}
// local wait, acquire at cluster scope (orders remote DSMEM stores)
__device__ __forceinline__ void mbar_wait(uint32_t a, int parity) {
    asm volatile(
        "{\n\t.reg .pred P;\n\t"
        "W_%=:\n\t"
        "mbarrier.try_wait.parity.acquire.cluster.shared::cta.b64 P, [%0], %1, 0x989680;\n\t"
        "@P bra.uni D_%=;\n\t"
        "bra.uni W_%=;\n\t"
        "D_%=:\n\t}"
        :: "r"(a), "r"(parity) : "memory");
}

// ---------------- Phase 1: band Gram (pre-scaled), 512 CTAs x 256 thr --------
__global__ __launch_bounds__(256) void gram_kernel(const float* __restrict__ xs) {
    __shared__ float Bs[64][65];
    const int m = blockIdx.x, t = threadIdx.x;
    const int r0 = (t & 7) * 4, j0 = (t >> 3) * 2;
    const int baserow = 32 * m - 32;
    float acc[4][2] = {{0.f,0.f},{0.f,0.f},{0.f,0.f},{0.f,0.f}};
    for (int ch = 0; ch < DDIM / 64; ch++) {
#pragma unroll
        for (int q = 0; q < 4; q++) {
            int id = t + 256 * q;
            int row = id >> 4, c4 = (id & 15) * 4;
            int arow = baserow + row;
            float4 v = make_float4(0.f, 0.f, 0.f, 0.f);
            if (arow >= 0)
                v = *(const float4*)(xs + (size_t)arow * DDIM + ch * 64 + c4);
            Bs[row][c4+0]=v.x; Bs[row][c4+1]=v.y; Bs[row][c4+2]=v.z; Bs[row][c4+3]=v.w;
        }
        __syncthreads();
#pragma unroll 8
        for (int d = 0; d < 64; d++) {
            float a0=Bs[32+r0+0][d], a1=Bs[32+r0+1][d], a2=Bs[32+r0+2][d], a3=Bs[32+r0+3][d];
            float b0=Bs[j0+0][d], b1=Bs[j0+1][d];
            acc[0][0]=fmaf(a0,b0,acc[0][0]); acc[1][0]=fmaf(a1,b0,acc[1][0]);
            acc[2][0]=fmaf(a2,b0,acc[2][0]); acc[3][0]=fmaf(a3,b0,acc[3][0]);
            acc[0][1]=fmaf(a0,b1,acc[0][1]); acc[1][1]=fmaf(a1,b1,acc[1][1]);
            acc[2][1]=fmaf(a2,b1,acc[2][1]); acc[3][1]=fmaf(a3,b1,acc[3][1]);
        }
        __syncthreads();
    }
    float* dst = g_WB + (size_t)m * (64 * BLK);
#pragma unroll
    for (int rr = 0; rr < 4; rr++)
#pragma unroll
        for (int jj = 0; jj < 2; jj++)
            dst[(j0 + jj) * BLK + (r0 + rr)] = (0.25f * ETA) * acc[rr][jj];
}

// ---------------- Phase 2 device pieces ----------------
__device__ __forceinline__ void matvec_push(const float* __restrict__ xs,
        const float* __restrict__ th, int blk, int wwarp, int lane,
        int colbase, uint32_t dst, uint32_t dready_rem) {
    const float4* th4 = (const float4*)th;
    float4 t0 = th4[lane], t1 = th4[lane+32], t2 = th4[lane+64], t3 = th4[lane+96];
    float s[4];
#pragma unroll
    for (int rr = 0; rr < 4; rr++) {
        const float4* xr = (const float4*)(xs + ((size_t)blk * BLK + 4*wwarp + rr) * DDIM + colbase);
        float4 a = xr[lane], b = xr[lane+32], c = xr[lane+64], d = xr[lane+96];
        float p0 = a.x*t0.x; p0=fmaf(a.y,t0.y,p0); p0=fmaf(a.z,t0.z,p0); p0=fmaf(a.w,t0.w,p0);
        float p1 = b.x*t1.x; p1=fmaf(b.y,t1.y,p1); p1=fmaf(b.z,t1.z,p1); p1=fmaf(b.w,t1.w,p1);
        float p2 = c.x*t2.x; p2=fmaf(c.y,t2.y,p2); p2=fmaf(c.z,t2.z,p2); p2=fmaf(c.w,t2.w,p2);
        float p3 = d.x*t3.x; p3=fmaf(d.y,t3.y,p3); p3=fmaf(d.z,t3.z,p3); p3=fmaf(d.w,t3.w,p3);
        s[rr] = (p0 + p1) + (p2 + p3);
    }
#pragma unroll
    for (int rr = 0; rr < 4; rr++) {
        s[rr] += __shfl_xor_sync(0xffffffffu, s[rr], 16);
        s[rr] += __shfl_xor_sync(0xffffffffu, s[rr], 8);
        s[rr] += __shfl_xor_sync(0xffffffffu, s[rr], 4);
        s[rr] += __shfl_xor_sync(0xffffffffu, s[rr], 2);
        s[rr] += __shfl_xor_sync(0xffffffffu, s[rr], 1);
    }
    if (lane == 0) {
        st_cluster_f32(dst + 0u,  0.5f * s[0]);
        st_cluster_f32(dst + 4u,  0.5f * s[1]);
        st_cluster_f32(dst + 8u,  0.5f * s[2]);
        st_cluster_f32(dst + 12u, 0.5f * s[3]);
        mbar_arrive_rel(dready_rem);
    }
}

__device__ __forceinline__ void apply_update(const float* __restrict__ xs,
        float* __restrict__ th, const float* __restrict__ cp,
        int blk, int widx, int colbase) {
    float2 t = *(float2*)(th + 2*widx);
    const float* xp = xs + (size_t)blk * BLK * DDIM + colbase + 2*widx;
#pragma unroll 8
    for (int j = 0; j < BLK; j++) {
        float c = cp[j];
        float2 xv = *(const float2*)(xp + (size_t)j * DDIM);
        t.x = fmaf(c, xv.x, t.x);
        t.y = fmaf(c, xv.y, t.y);
    }
    *(float2*)(th + 2*widx) = t;
}

// chain segment: critical path per step = tanh(16) -> shfl(26) -> fma(4)
__device__ __forceinline__ void chain_seg(
        int s, int lane, int pd, uint32_t mbar_d_loc,
        const float* __restrict__ dpart_b, float* __restrict__ cbuf_b,
        float* __restrict__ wbuf,
        uint32_t cb_r1, uint32_t cb_r2, uint32_t cb_r3, uint32_t cr_mine) {
    const float* G = g_WB + (size_t)s * (64 * BLK);
    float Gc[32], Gi[32];
#pragma unroll
    for (int j = 0; j < 32; j++) Gc[j] = G[j * 32 + lane];
#pragma unroll
    for (int j = 0; j < 32; j++) Gi[j] = G[(32 + j) * 32 + lane];

    // prev-block correction: sum_j w_j * Gc[j] (4 parallel chains)
    float a0=0.f, a1=0.f, a2=0.f, a3=0.f;
#pragma unroll
    for (int i = 0; i < 8; i++) {
        float4 q = *(const float4*)&wbuf[4 * i];
        a0 = fmaf(q.x, Gc[4*i+0], a0);
        a1 = fmaf(q.y, Gc[4*i+1], a1);
        a2 = fmaf(q.z, Gc[4*i+2], a2);
        a3 = fmaf(q.w, Gc[4*i+3], a3);
    }
    float corr = (a0 + a1) + (a2 + a3);

    mbar_wait(mbar_d_loc, pd);   // G loads + corr overlap this wait

    float h = (dpart_b[lane] + dpart_b[32 + lane]) +
              (dpart_b[64 + lane] + dpart_b[96 + lane]);
    h += corr;

    float t = fast_tanh(h);
    float myt = 0.f;
#pragma unroll
    for (int r = 1; r < 32; r++) {
        float tb = __shfl_sync(0xffffffffu, t, r - 1);
        myt = (lane == r - 1) ? t : myt;          // capture before overwrite
        h = fmaf(tb, -Gi[r - 1], h + Gi[r - 1]);  // (1-t)*G', h+G' off-path
        t = fast_tanh(h);
    }
    myt = (lane == 31) ? t : myt;

    float w = 1.0f - myt;
    wbuf[lane] = w;                 // for next segment's correction
    float c = 0.5f * ETA * w;       // theta-update coefficient
    cbuf_b[lane] = c;               // local CTA0 copy
    st_cluster_f32(cb_r1 + (uint32_t)lane * 4u, c);
    st_cluster_f32(cb_r2 + (uint32_t)lane * 4u, c);
    st_cluster_f32(cb_r3 + (uint32_t)lane * 4u, c);
    __syncwarp();
    if (lane < 4) mbar_arrive_rel(cr_mine);
    __syncwarp();
}

// ---------------- Phase 2: cluster scan ----------------
__global__ __launch_bounds__(NTH, 1) __cluster_dims__(NC, 1, 1)
void scan_kernel(const float* __restrict__ theta0, const float* __restrict__ xs,
                 float* __restrict__ out) {
    __shared__ float th[SLICE];
    __shared__ float cbuf[2][BLK];
    __shared__ float dpart[2][NC][BLK];
    __shared__ float wbuf[BLK];
    __shared__ alignas(8) unsigned long long mbar_d[2];  // CTA0: 32 arrivals
    __shared__ alignas(8) unsigned long long mbar_c[2];  // per CTA: 1 arrival

    const int tid = threadIdx.x;
    uint32_t rank; asm("mov.u32 %0, %%cluster_ctarank;" : "=r"(rank));
    const int colbase = (int)rank * SLICE;
    const int wwarp = (tid >> 5) - 1;
    const int lane = tid & 31;

    if (tid == 0) {
        mbar_init(smem_u32(&mbar_d[0]), 32);
        mbar_init(smem_u32(&mbar_d[1]), 32);
        mbar_init(smem_u32(&mbar_c[0]), 1);
        mbar_init(smem_u32(&mbar_c[1]), 1);
    }
    if (rank == 0 && tid < BLK) wbuf[tid] = 0.f;
    for (int i = tid; i < SLICE; i += NTH) th[i] = theta0[colbase + i];
    __syncthreads();
    cluster_sync_();   // publish mbarrier inits before any remote arrive

    if (tid < 32) {
        // ---------------- chain warp (CTA0) / idle (others) ----------------
        if (rank == 0) {
            const uint32_t md0 = smem_u32(&mbar_d[0]);
            const uint32_t md1 = smem_u32(&mbar_d[1]);
            const uint32_t cb0_1 = mapa_rk(smem_u32(&cbuf[0][0]), 1);
            const uint32_t cb0_2 = mapa_rk(smem_u32(&cbuf[0][0]), 2);
            const uint32_t cb0_3 = mapa_rk(smem_u32(&cbuf[0][0]), 3);
            const uint32_t cb1_1 = mapa_rk(smem_u32(&cbuf[1][0]), 1);
            const uint32_t cb1_2 = mapa_rk(smem_u32(&cbuf[1][0]), 2);
            const uint32_t cb1_3 = mapa_rk(smem_u32(&cbuf[1][0]), 3);
            const uint32_t rkm = (lane < 4) ? (uint32_t)lane : 3u;
            const uint32_t cr0_mine = mapa_rk(smem_u32(&mbar_c[0]), rkm);
            const uint32_t cr1_mine = mapa_rk(smem_u32(&mbar_c[1]), rkm);
            int pd0 = 0, pd1 = 0;
            for (int s2 = 0; s2 < NBLK; s2 += 2) {
                chain_seg(s2,     lane, pd0, md0, &dpart[0][0][0], &cbuf[0][0],
                          wbuf, cb0_1, cb0_2, cb0_3, cr0_mine);
                pd0 ^= 1;
                chain_seg(s2 + 1, lane, pd1, md1, &dpart[1][0][0], &cbuf[1][0],
                          wbuf, cb1_1, cb1_2, cb1_3, cr1_mine);
                pd1 ^= 1;
            }
        }
    } else {
        // ---------------- worker warps (all CTAs) ----------------
        const uint32_t dst0 = mapa_rk(smem_u32(&dpart[0][rank][4 * wwarp]), 0);
        const uint32_t dst1 = mapa_rk(smem_u32(&dpart[1][rank][4 * wwarp]), 0);
        const uint32_t dr0  = mapa_rk(smem_u32(&mbar_d[0]), 0);
        const uint32_t dr1  = mapa_rk(smem_u32(&mbar_d[1]), 0);
        const uint32_t mc0  = smem_u32(&mbar_c[0]);
        const uint32_t mc1  = smem_u32(&mbar_c[1]);
        const int widx = tid - 32;
        int pc0 = 0, pc1 = 0;

        // priming: d_0 -> dpart[0]
        matvec_push(xs, th, 0, wwarp, lane, colbase, dst0, dr0);
        asm volatile("bar.sync 1, 256;" ::: "memory");

        for (int s2 = 0; s2 < NBLK; s2 += 2) {
            // s = s2 (even): apply block s-1 (c in cbuf[1]), matvec s+1 -> buf1
            if (s2 > 0) {
                mbar_wait(mc1, pc1); pc1 ^= 1;
                apply_update(xs, th, &cbuf[1][0], s2 - 1, widx, colbase);
            }
            asm volatile("bar.sync 1, 256;" ::: "memory");
            matvec_push(xs, th, s2 + 1, wwarp, lane, colbase, dst1, dr1);
            asm volatile("bar.sync 1, 256;" ::: "memory");

            // s = s2+1 (odd): apply block s2 (c in cbuf[0]), matvec s2+2 -> buf0
            mbar_wait(mc0, pc0); pc0 ^= 1;
            apply_update(xs, th, &cbuf[0][0], s2, widx, colbase);
            asm volatile("bar.sync 1, 256;" ::: "memory");
            if (s2 + 2 < NBLK) {
                matvec_push(xs, th, s2 + 2, wwarp, lane, colbase, dst0, dr0);
                asm volatile("bar.sync 1, 256;" ::: "memory");
            }
        }
        // final: apply block NBLK-1 (odd -> cbuf[1])
        mbar_wait(mc1, pc1);
        apply_update(xs, th, &cbuf[1][0], NBLK - 1, widx, colbase);
    }

    __syncthreads();
    for (int i = tid; i < SLICE; i += NTH) out[colbase + i] = th[i];
    cluster_sync_();   // no CTA exits while remote traffic may be in flight
}

extern "C" void kernel_launch(void* const* d_in, const int* in_sizes, int n_in,
                              void* d_out, int out_size) {
    const float* theta = (const float*)d_in[0];
    const float* xs    = (const float*)d_in[1];
    if (in_sizes[0] != DDIM) {
        theta = (const float*)d_in[1];
        xs    = (const float*)d_in[0];
    }
    gram_kernel<<<NBLK, 256>>>(xs);
    scan_kernel<<<NC, NTH>>>(theta, xs, (float*)d_out);
}

// round 9
// speedup vs baseline: 1.0052x; 1.0052x over previous
#include <cuda_runtime.h>
#include <cstdint>

// Blocked online logistic-SGD scan, lag-2 decoupled pipeline.
// Band Gram (width 96, pre-scaled by ETA/4):
//   g_WB[m][j][r]: j in [0,32): block m-2 | [32,64): block m-1 | [64,96): intra m
// Phase 2 (4-CTA cluster):
//   chain (CTA0 warp0): per segment s needs d = 0.5<x_k, A_{s-2}> from workers,
//     corrects dist-2/dist-1 via its own w history (wring, same warp), runs the
//     31-step tanh->shfl->fma recurrence. G staged via cp.async double buffer.
//   workers (warps 1-8, all CTAs): tick t = apply c^{(t-3)}, matvec block t with
//     theta = A_{t-2}, DSMEM-push d partials. 3 segments of slack -> off the
//     critical cycle. Ring-4 dpart/cbuf/mbarriers, arithmetic slot addressing.

#define DDIM 2048
#define NSTEPS 16384
#define BLK 32
#define NBLK 512
#define ETA 0.01f
#define NC 4
#define SLICE 512
#define NTH 288
#define BW 96

__device__ float g_WB[(size_t)NBLK * BW * BLK];   // 6.3 MB scratch

__device__ __forceinline__ float fast_tanh(float x) {
    float r; asm("tanh.approx.f32 %0, %1;" : "=f"(r) : "f"(x)); return r;
}
__device__ __forceinline__ uint32_t smem_u32(const void* p) {
    return (uint32_t)__cvta_generic_to_shared(p);
}
__device__ __forceinline__ uint32_t mapa_rk(uint32_t a, uint32_t rk) {
    uint32_t r; asm("mapa.shared::cluster.u32 %0, %1, %2;" : "=r"(r) : "r"(a), "r"(rk));
    return r;
}
__device__ __forceinline__ void st_cluster_f32(uint32_t a, float v) {
    asm volatile("st.shared::cluster.f32 [%0], %1;" :: "r"(a), "f"(v) : "memory");
}
__device__ __forceinline__ void cluster_sync_() {
    asm volatile("barrier.cluster.arrive.aligned;" ::: "memory");
    asm volatile("barrier.cluster.wait.aligned;" ::: "memory");
}
__device__ __forceinline__ void mbar_init(uint32_t a, uint32_t cnt) {
    asm volatile("mbarrier.init.shared.b64 [%0], %1;" :: "r"(a), "r"(cnt) : "memory");
}
__device__ __forceinline__ void mbar_arrive_rel(uint32_t a) {
    asm volatile("mbarrier.arrive.release.cluster.shared::cluster.b64 _, [%0];"
                 :: "r"(a) : "memory");
}
__device__ __forceinline__ void mbar_wait(uint32_t a, int parity) {
    asm volatile(
        "{\n\t.reg .pred P;\n\t"
        "W_%=:\n\t"
        "mbarrier.try_wait.parity.acquire.cluster.shared::cta.b64 P, [%0], %1, 0x989680;\n\t"
        "@P bra.uni D_%=;\n\t"
        "bra.uni W_%=;\n\t"
        "D_%=:\n\t}"
        :: "r"(a), "r"(parity) : "memory");
}
__device__ __forceinline__ void cp_async16(uint32_t saddr, const void* gptr) {
    asm volatile("cp.async.cg.shared.global [%0], [%1], 16;"
                 :: "r"(saddr), "l"(gptr) : "memory");
}
__device__ __forceinline__ void cp_commit() {
    asm volatile("cp.async.commit_group;" ::: "memory");
}
__device__ __forceinline__ void cp_wait0() {
    asm volatile("cp.async.wait_group 0;" ::: "memory");
}

// ---------------- Phase 1: band-96 Gram, 512 CTAs x 256 thr ----------------
// Tile rows 0..95 = global rows 32*m - 64 + row (zero-filled below 0).
__global__ __launch_bounds__(256) void gram_kernel(const float* __restrict__ xs) {
    __shared__ float Bs[96][65];
    const int m = blockIdx.x, t = threadIdx.x;
    const int r0 = (t & 7) * 4;        // 4 rows of block m (tile rows 64+r0..)
    const int j0 = (t >> 3) * 3;       // 3 band columns
    const int baserow = 32 * m - 64;
    float acc[4][3];
#pragma unroll
    for (int a = 0; a < 4; a++)
#pragma unroll
        for (int b = 0; b < 3; b++) acc[a][b] = 0.f;

    for (int ch = 0; ch < DDIM / 64; ch++) {
#pragma unroll
        for (int q = 0; q < 6; q++) {
            int id = t + 256 * q;          // 0..1535
            int row = id >> 4, c4 = (id & 15) * 4;
            int arow = baserow + row;
            float4 v = make_float4(0.f, 0.f, 0.f, 0.f);
            if (arow >= 0)
                v = *(const float4*)(xs + (size_t)arow * DDIM + ch * 64 + c4);
            Bs[row][c4+0]=v.x; Bs[row][c4+1]=v.y; Bs[row][c4+2]=v.z; Bs[row][c4+3]=v.w;
        }
        __syncthreads();
#pragma unroll 8
        for (int d = 0; d < 64; d++) {
            float a0=Bs[64+r0+0][d], a1=Bs[64+r0+1][d], a2=Bs[64+r0+2][d], a3=Bs[64+r0+3][d];
            float b0=Bs[j0+0][d], b1=Bs[j0+1][d], b2=Bs[j0+2][d];
            acc[0][0]=fmaf(a0,b0,acc[0][0]); acc[1][0]=fmaf(a1,b0,acc[1][0]);
            acc[2][0]=fmaf(a2,b0,acc[2][0]); acc[3][0]=fmaf(a3,b0,acc[3][0]);
            acc[0][1]=fmaf(a0,b1,acc[0][1]); acc[1][1]=fmaf(a1,b1,acc[1][1]);
            acc[2][1]=fmaf(a2,b1,acc[2][1]); acc[3][1]=fmaf(a3,b1,acc[3][1]);
            acc[0][2]=fmaf(a0,b2,acc[0][2]); acc[1][2]=fmaf(a1,b2,acc[1][2]);
            acc[2][2]=fmaf(a2,b2,acc[2][2]); acc[3][2]=fmaf(a3,b2,acc[3][2]);
        }
        __syncthreads();
    }
    float* dst = g_WB + (size_t)m * (BW * BLK);
#pragma unroll
    for (int rr = 0; rr < 4; rr++)
#pragma unroll
        for (int jj = 0; jj < 3; jj++)
            dst[(j0 + jj) * BLK + (r0 + rr)] = (0.25f * ETA) * acc[rr][jj];
}

// ---------------- Phase 2 worker pieces ----------------
__device__ __forceinline__ void matvec_push(const float* __restrict__ xs,
        const float* __restrict__ th, int blk, int wwarp, int lane,
        int colbase, uint32_t dst, uint32_t dready_rem) {
    const float4* th4 = (const float4*)th;
    float4 t0 = th4[lane], t1 = th4[lane+32], t2 = th4[lane+64], t3 = th4[lane+96];
    float s[4];
#pragma unroll
    for (int rr = 0; rr < 4; rr++) {
        const float4* xr = (const float4*)(xs + ((size_t)blk * BLK + 4*wwarp + rr) * DDIM + colbase);
        float4 a = xr[lane], b = xr[lane+32], c = xr[lane+64], d = xr[lane+96];
        float p0 = a.x*t0.x; p0=fmaf(a.y,t0.y,p0); p0=fmaf(a.z,t0.z,p0); p0=fmaf(a.w,t0.w,p0);
        float p1 = b.x*t1.x; p1=fmaf(b.y,t1.y,p1); p1=fmaf(b.z,t1.z,p1); p1=fmaf(b.w,t1.w,p1);
        float p2 = c.x*t2.x; p2=fmaf(c.y,t2.y,p2); p2=fmaf(c.z,t2.z,p2); p2=fmaf(c.w,t2.w,p2);
        float p3 = d.x*t3.x; p3=fmaf(d.y,t3.y,p3); p3=fmaf(d.z,t3.z,p3); p3=fmaf(d.w,t3.w,p3);
        s[rr] = (p0 + p1) + (p2 + p3);
    }
#pragma unroll
    for (int rr = 0; rr < 4; rr++) {
        s[rr] += __shfl_xor_sync(0xffffffffu, s[rr], 16);
        s[rr] += __shfl_xor_sync(0xffffffffu, s[rr], 8);
        s[rr] += __shfl_xor_sync(0xffffffffu, s[rr], 4);
        s[rr] += __shfl_xor_sync(0xffffffffu, s[rr], 2);
        s[rr] += __shfl_xor_sync(0xffffffffu, s[rr], 1);
    }
    if (lane == 0) {
        st_cluster_f32(dst + 0u,  0.5f * s[0]);
        st_cluster_f32(dst + 4u,  0.5f * s[1]);
        st_cluster_f32(dst + 8u,  0.5f * s[2]);
        st_cluster_f32(dst + 12u, 0.5f * s[3]);
        mbar_arrive_rel(dready_rem);
    }
}

__device__ __forceinline__ void apply_update(const float* __restrict__ xs,
        float* __restrict__ th, const float* __restrict__ cp,
        int blk, int widx, int colbase) {
    float2 t = *(float2*)(th + 2*widx);
    const float* xp = xs + (size_t)blk * BLK * DDIM + colbase + 2*widx;
#pragma unroll 8
    for (int j = 0; j < BLK; j++) {
        float c = cp[j];
        float2 xv = *(const float2*)(xp + (size_t)j * DDIM);
        t.x = fmaf(c, xv.x, t.x);
        t.y = fmaf(c, xv.y, t.y);
    }
    *(float2*)(th + 2*widx) = t;
}

// ---------------- Phase 2: cluster scan ----------------
__global__ __launch_bounds__(NTH, 1) __cluster_dims__(NC, 1, 1)
void scan_kernel(const float* __restrict__ theta0, const float* __restrict__ xs,
                 float* __restrict__ out) {
    __shared__ float th[SLICE];
    __shared__ alignas(16) float Gsm[2][BW * BLK];   // 24 KB, cp.async staged
    __shared__ float cbuf[4][BLK];
    __shared__ float dpart[4][NC][BLK];
    __shared__ alignas(16) float wring[2][BLK];
    __shared__ alignas(8) unsigned long long mbar_d[4];  // CTA0: 32 arrivals each
    __shared__ alignas(8) unsigned long long mbar_c[4];  // per CTA: 1 arrival each

    const int tid = threadIdx.x;
    uint32_t rank; asm("mov.u32 %0, %%cluster_ctarank;" : "=r"(rank));
    const int colbase = (int)rank * SLICE;
    const int wwarp = (tid >> 5) - 1;
    const int lane = tid & 31;

    if (tid == 0) {
#pragma unroll
        for (int i = 0; i < 4; i++) {
            mbar_init(smem_u32(&mbar_d[i]), 32);
            mbar_init(smem_u32(&mbar_c[i]), 1);
        }
    }
    if (rank == 0 && tid < 64) ((float*)wring)[tid] = 0.f;
    for (int i = tid; i < SLICE; i += NTH) th[i] = theta0[colbase + i];
    __syncthreads();
    cluster_sync_();   // publish mbarrier inits before any remote arrive

    if (tid < 32) {
        if (rank == 0) {
            // ---------------- chain warp ----------------
            const uint32_t md_base = smem_u32(&mbar_d[0]);
            const uint32_t cb_base = smem_u32(&cbuf[0][0]);
            const uint32_t cb1 = mapa_rk(cb_base, 1);
            const uint32_t cb2 = mapa_rk(cb_base, 2);
            const uint32_t cb3 = mapa_rk(cb_base, 3);
            const uint32_t rkm = (lane < 4) ? (uint32_t)lane : 0u;
            const uint32_t cr_mine = mapa_rk(smem_u32(&mbar_c[0]), rkm);

            // prime: G(0) -> Gsm[0]
            {
                const char* gs = (const char*)g_WB;
                uint32_t gd = smem_u32(&Gsm[0][0]);
#pragma unroll
                for (int i = 0; i < 24; i++)
                    cp_async16(gd + (uint32_t)(lane + i*32)*16u, gs + (size_t)(lane + i*32)*16);
                cp_commit();
            }

            for (int s = 0; s < NBLK; s++) {
                cp_wait0();
                __syncwarp();
                if (s + 1 < NBLK) {   // prefetch G(s+1)
                    const char* gs = (const char*)(g_WB + (size_t)(s+1) * BW * BLK);
                    uint32_t gd = smem_u32(&Gsm[(s+1)&1][0]);
#pragma unroll
                    for (int i = 0; i < 24; i++)
                        cp_async16(gd + (uint32_t)(lane + i*32)*16u, gs + (size_t)(lane + i*32)*16);
                    cp_commit();
                }
                const float* Gb = &Gsm[s & 1][0];
                float Gd2[32], Gd1[32], Gi[32];
#pragma unroll
                for (int j = 0; j < 32; j++) Gd2[j] = Gb[j * 32 + lane];
#pragma unroll
                for (int j = 0; j < 32; j++) Gd1[j] = Gb[(32 + j) * 32 + lane];
#pragma unroll
                for (int j = 0; j < 32; j++) Gi[j]  = Gb[(64 + j) * 32 + lane];

                // corrections from w^(s-2) (wring[s&1]) and w^(s-1) (wring[(s+1)&1])
                const float4* w2 = (const float4*)&wring[s & 1][0];
                const float4* w1 = (const float4*)&wring[(s + 1) & 1][0];
                float a0=0.f, a1=0.f, a2=0.f, a3=0.f;
#pragma unroll
                for (int i = 0; i < 8; i++) {
                    float4 q = w2[i];
                    a0 = fmaf(q.x, Gd2[4*i+0], a0); a1 = fmaf(q.y, Gd2[4*i+1], a1);
                    a2 = fmaf(q.z, Gd2[4*i+2], a2); a3 = fmaf(q.w, Gd2[4*i+3], a3);
                }
#pragma unroll
                for (int i = 0; i < 8; i++) {
                    float4 q = w1[i];
                    a0 = fmaf(q.x, Gd1[4*i+0], a0); a1 = fmaf(q.y, Gd1[4*i+1], a1);
                    a2 = fmaf(q.z, Gd1[4*i+2], a2); a3 = fmaf(q.w, Gd1[4*i+3], a3);
                }
                float corr = (a0 + a1) + (a2 + a3);

                mbar_wait(md_base + (uint32_t)(s & 3) * 8u, (s >> 2) & 1);
                const float* dp = &dpart[s & 3][0][0];
                float h = ((dp[lane] + dp[32 + lane]) + (dp[64 + lane] + dp[96 + lane])) + corr;

                float t = fast_tanh(h);
                float myt = 0.f;
#pragma unroll
                for (int r = 1; r < 32; r++) {
                    float tb = __shfl_sync(0xffffffffu, t, r - 1);
                    myt = (lane == r - 1) ? t : myt;
                    h = fmaf(tb, -Gi[r - 1], h + Gi[r - 1]);
                    t = fast_tanh(h);
                }
                myt = (lane == 31) ? t : myt;

                float w = 1.0f - myt;
                wring[s & 1][lane] = w;
                float c = 0.5f * ETA * w;
                cbuf[s & 3][lane] = c;
                uint32_t coff = (uint32_t)(s & 3) * 128u + (uint32_t)lane * 4u;
                st_cluster_f32(cb1 + coff, c);
                st_cluster_f32(cb2 + coff, c);
                st_cluster_f32(cb3 + coff, c);
                __syncwarp();
                if (lane < 4) mbar_arrive_rel(cr_mine + (uint32_t)(s & 3) * 8u);
                __syncwarp();
            }
        }
        // rank != 0, warp0: idle
    } else {
        // ---------------- worker warps (all CTAs) ----------------
        const uint32_t dst_base = mapa_rk(smem_u32(&dpart[0][rank][4 * wwarp]), 0);
        const uint32_t dr_base  = mapa_rk(smem_u32(&mbar_d[0]), 0);
        const uint32_t mc_base  = smem_u32(&mbar_c[0]);
        const int widx = tid - 32;

        for (int t = 0; t < NBLK; t++) {
            if (t >= 3) {
                int u = t - 3;
                mbar_wait(mc_base + (uint32_t)(u & 3) * 8u, (u >> 2) & 1);
                apply_update(xs, th, &cbuf[u & 3][0], u, widx, colbase);
            }
            asm volatile("bar.sync 1, 256;" ::: "memory");
            matvec_push(xs, th, t, wwarp, lane, colbase,
                        dst_base + (uint32_t)(t & 3) * (NC * BLK * 4),
                        dr_base + (uint32_t)(t & 3) * 8u);
            asm volatile("bar.sync 1, 256;" ::: "memory");
        }
        for (int t = NBLK; t < NBLK + 3; t++) {
            int u = t - 3;
            mbar_wait(mc_base + (uint32_t)(u & 3) * 8u, (u >> 2) & 1);
            apply_update(xs, th, &cbuf[u & 3][0], u, widx, colbase);
            asm volatile("bar.sync 1, 256;" ::: "memory");
        }
    }

    __syncthreads();
    for (int i = tid; i < SLICE; i += NTH) out[colbase + i] = th[i];
    cluster_sync_();
}

extern "C" void kernel_launch(void* const* d_in, const int* in_sizes, int n_in,
                              void* d_out, int out_size) {
    const float* theta = (const float*)d_in[0];
    const float* xs    = (const float*)d_in[1];
    if (in_sizes[0] != DDIM) {
        theta = (const float*)d_in[1];
        xs    = (const float*)d_in[0];
    }
    gram_kernel<<<NBLK, 256>>>(xs);
    scan_kernel<<<NC, NTH>>>(theta, xs, (float*)d_out);
}

// round 10
// speedup vs baseline: 1.3627x; 1.3556x over previous
#include <cuda_runtime.h>
#include <cstdint>

// Fused blocked online logistic-SGD scan.
// One kernel, 65 clusters x 8 CTAs:
//   cluster 0          : scan (chain warp + 8 worker warps/CTA + prefetch warp)
//   CTAs 8..519        : band-96 Gram for block m = bid-8, publish release-flag.
// Band Gram pre-scaled by ETA/4: g_WB[m][j][r], j in [0,32): block m-2,
//   [32,64): block m-1, [64,96): intra. Chain corrects dist-1/2 from its own
//   w-history; workers run theta lag-3 (apply c^{(t-3)}, matvec block t).

#define DDIM 2048
#define NSTEPS 16384
#define BLK 32
#define NBLK 512
#define ETA 0.01f
#define NC 8
#define SLICE 256
#define NTH 320
#define BW 96

__device__ float g_WB[(size_t)NBLK * BW * BLK];
__device__ int g_flag[NBLK];   // zero-init at load; set-once (idempotent across replays)

__device__ __forceinline__ float fast_tanh(float x) {
    float r; asm("tanh.approx.f32 %0, %1;" : "=f"(r) : "f"(x)); return r;
}
__device__ __forceinline__ uint32_t smem_u32(const void* p) {
    return (uint32_t)__cvta_generic_to_shared(p);
}
__device__ __forceinline__ uint32_t mapa_rk(uint32_t a, uint32_t rk) {
    uint32_t r; asm("mapa.shared::cluster.u32 %0, %1, %2;" : "=r"(r) : "r"(a), "r"(rk));
    return r;
}
__device__ __forceinline__ void st_cluster_f32(uint32_t a, float v) {
    asm volatile("st.shared::cluster.f32 [%0], %1;" :: "r"(a), "f"(v) : "memory");
}
__device__ __forceinline__ void cluster_sync_() {
    asm volatile("barrier.cluster.arrive.aligned;" ::: "memory");
    asm volatile("barrier.cluster.wait.aligned;" ::: "memory");
}
__device__ __forceinline__ void mbar_init(uint32_t a, uint32_t cnt) {
    asm volatile("mbarrier.init.shared.b64 [%0], %1;" :: "r"(a), "r"(cnt) : "memory");
}
__device__ __forceinline__ void mbar_arrive_rel(uint32_t a) {
    asm volatile("mbarrier.arrive.release.cluster.shared::cluster.b64 _, [%0];"
                 :: "r"(a) : "memory");
}
__device__ __forceinline__ void mbar_arrive_local(uint32_t a) {
    asm volatile("mbarrier.arrive.shared.b64 _, [%0];" :: "r"(a) : "memory");
}
__device__ __forceinline__ void mbar_wait(uint32_t a, int parity) {
    asm volatile(
        "{\n\t.reg .pred P;\n\t"
        "W_%=:\n\t"
        "mbarrier.try_wait.parity.acquire.cluster.shared::cta.b64 P, [%0], %1, 0x989680;\n\t"
        "@P bra.uni D_%=;\n\t"
        "bra.uni W_%=;\n\t"
        "D_%=:\n\t}"
        :: "r"(a), "r"(parity) : "memory");
}
__device__ __forceinline__ void cp_async16(uint32_t saddr, const void* gptr) {
    asm volatile("cp.async.cg.shared.global [%0], [%1], 16;"
                 :: "r"(saddr), "l"(gptr) : "memory");
}
__device__ __forceinline__ void cp_commit() { asm volatile("cp.async.commit_group;" ::: "memory"); }
__device__ __forceinline__ void cp_wait0()  { asm volatile("cp.async.wait_group 0;" ::: "memory"); }

struct ScanSh {
    float th[SLICE];
    float cbuf[4][BLK];
    float dpart[4][NC][BLK];
    float wring[2][BLK];
    unsigned long long mbar_d[4];    // 64 arrivals (8 warps x 8 CTAs)
    unsigned long long mbar_c[4];    // 1 arrival each
    unsigned long long mbar_pf[2];   // prefetch-done
    unsigned long long mbar_cons[2]; // chain-consumed
    alignas(16) float Gsm[2][BW * BLK];
};
struct GramSh { float Bs[96][65]; };
union Sh { ScanSh s; GramSh g; };

__global__ __launch_bounds__(NTH, 1) __cluster_dims__(NC, 1, 1)
void fused_kernel(const float* __restrict__ theta0, const float* __restrict__ xs,
                  float* __restrict__ out) {
    __shared__ Sh u;
    const int tid = threadIdx.x;
    const int bid = blockIdx.x;

    if (bid >= NC) {
        // ================= GRAM role: block m = bid - NC =================
        const int m = bid - NC;
        const int baserow = 32 * m - 64;
        const int r0 = (tid & 7) * 4, j0 = (tid >> 3) * 3;
        const bool act = (tid < 256);
        float acc[4][3];
#pragma unroll
        for (int a = 0; a < 4; a++)
#pragma unroll
            for (int b = 0; b < 3; b++) acc[a][b] = 0.f;

        for (int ch = 0; ch < DDIM / 64; ch++) {
#pragma unroll
            for (int q = 0; q < 5; q++) {
                int id = tid + NTH * q;
                if (id < 1536) {
                    int row = id >> 4, c4 = (id & 15) * 4;
                    int arow = baserow + row;
                    float4 v = make_float4(0.f, 0.f, 0.f, 0.f);
                    if (arow >= 0)
                        v = *(const float4*)(xs + (size_t)arow * DDIM + ch * 64 + c4);
                    u.g.Bs[row][c4+0]=v.x; u.g.Bs[row][c4+1]=v.y;
                    u.g.Bs[row][c4+2]=v.z; u.g.Bs[row][c4+3]=v.w;
                }
            }
            __syncthreads();
            if (act) {
#pragma unroll 8
                for (int d = 0; d < 64; d++) {
                    float a0=u.g.Bs[64+r0+0][d], a1=u.g.Bs[64+r0+1][d];
                    float a2=u.g.Bs[64+r0+2][d], a3=u.g.Bs[64+r0+3][d];
                    float b0=u.g.Bs[j0+0][d], b1=u.g.Bs[j0+1][d], b2=u.g.Bs[j0+2][d];
                    acc[0][0]=fmaf(a0,b0,acc[0][0]); acc[1][0]=fmaf(a1,b0,acc[1][0]);
                    acc[2][0]=fmaf(a2,b0,acc[2][0]); acc[3][0]=fmaf(a3,b0,acc[3][0]);
                    acc[0][1]=fmaf(a0,b1,acc[0][1]); acc[1][1]=fmaf(a1,b1,acc[1][1]);
                    acc[2][1]=fmaf(a2,b1,acc[2][1]); acc[3][1]=fmaf(a3,b1,acc[3][1]);
                    acc[0][2]=fmaf(a0,b2,acc[0][2]); acc[1][2]=fmaf(a1,b2,acc[1][2]);
                    acc[2][2]=fmaf(a2,b2,acc[2][2]); acc[3][2]=fmaf(a3,b2,acc[3][2]);
                }
            }
            __syncthreads();
        }
        if (act) {
            float* dst = g_WB + (size_t)m * (BW * BLK);
#pragma unroll
            for (int rr = 0; rr < 4; rr++)
#pragma unroll
                for (int jj = 0; jj < 3; jj++)
                    dst[(j0 + jj) * BLK + (r0 + rr)] = (0.25f * ETA) * acc[rr][jj];
        }
        __syncthreads();
        if (tid == 0) {
            __threadfence();
            *(volatile int*)&g_flag[m] = 1;
        }
        return;
    }

    // ===================== SCAN role: cluster 0 =====================
    uint32_t rank; asm("mov.u32 %0, %%cluster_ctarank;" : "=r"(rank));
    const int colbase = (int)rank * SLICE;
    const int wid = tid >> 5;
    const int lane = tid & 31;

    if (tid == 0) {
#pragma unroll
        for (int i = 0; i < 4; i++) {
            mbar_init(smem_u32(&u.s.mbar_d[i]), 8 * NC);
            mbar_init(smem_u32(&u.s.mbar_c[i]), 1);
        }
#pragma unroll
        for (int i = 0; i < 2; i++) {
            mbar_init(smem_u32(&u.s.mbar_pf[i]), 1);
            mbar_init(smem_u32(&u.s.mbar_cons[i]), 1);
        }
    }
    if (rank == 0 && tid < 64) ((float*)u.s.wring)[tid] = 0.f;
    for (int i = tid; i < SLICE; i += NTH) u.s.th[i] = theta0[colbase + i];
    __syncthreads();
    cluster_sync_();

    if (wid == 0) {
        // ---------------- chain warp (rank 0 only) ----------------
        if (rank == 0) {
            const uint32_t md_base = smem_u32(&u.s.mbar_d[0]);
            const uint32_t pf_base = smem_u32(&u.s.mbar_pf[0]);
            const uint32_t cons_base = smem_u32(&u.s.mbar_cons[0]);
            const uint32_t cb_base = smem_u32(&u.s.cbuf[0][0]);
            uint32_t cbr[NC - 1];
#pragma unroll
            for (int r = 1; r < NC; r++) cbr[r - 1] = mapa_rk(cb_base, (uint32_t)r);
            const uint32_t rkm = (lane < NC) ? (uint32_t)lane : 0u;
            const uint32_t cr_mine = mapa_rk(smem_u32(&u.s.mbar_c[0]), rkm);

            for (int s = 0; s < NBLK; s++) {
                mbar_wait(pf_base + (uint32_t)(s & 1) * 8u, (s >> 1) & 1);
                const float* Gb = &u.s.Gsm[s & 1][0];
                float Gd2[32], Gd1[32], Gi[32];
#pragma unroll
                for (int j = 0; j < 32; j++) Gd2[j] = Gb[j * 32 + lane];
#pragma unroll
                for (int j = 0; j < 32; j++) Gd1[j] = Gb[(32 + j) * 32 + lane];
#pragma unroll
                for (int j = 0; j < 32; j++) Gi[j]  = Gb[(64 + j) * 32 + lane];

                const float4* w2 = (const float4*)&u.s.wring[s & 1][0];
                const float4* w1 = (const float4*)&u.s.wring[(s + 1) & 1][0];
                float a0=0.f, a1=0.f, a2=0.f, a3=0.f;
#pragma unroll
                for (int i = 0; i < 8; i++) {
                    float4 q = w2[i];
                    a0 = fmaf(q.x, Gd2[4*i+0], a0); a1 = fmaf(q.y, Gd2[4*i+1], a1);
                    a2 = fmaf(q.z, Gd2[4*i+2], a2); a3 = fmaf(q.w, Gd2[4*i+3], a3);
                }
#pragma unroll
                for (int i = 0; i < 8; i++) {
                    float4 q = w1[i];
                    a0 = fmaf(q.x, Gd1[4*i+0], a0); a1 = fmaf(q.y, Gd1[4*i+1], a1);
                    a2 = fmaf(q.z, Gd1[4*i+2], a2); a3 = fmaf(q.w, Gd1[4*i+3], a3);
                }
                float corr = (a0 + a1) + (a2 + a3);

                mbar_wait(md_base + (uint32_t)(s & 3) * 8u, (s >> 2) & 1);
                const float* dp = &u.s.dpart[s & 3][0][0];
                float h = ((dp[lane] + dp[32 + lane]) + (dp[64 + lane] + dp[96 + lane]))
                        + ((dp[128 + lane] + dp[160 + lane]) + (dp[192 + lane] + dp[224 + lane]))
                        + corr;

                float t = fast_tanh(h);
                float myt = 0.f;
#pragma unroll
                for (int r = 1; r < 32; r++) {
                    float tb = __shfl_sync(0xffffffffu, t, r - 1);
                    myt = (lane == r - 1) ? t : myt;
                    h = fmaf(tb, -Gi[r - 1], h + Gi[r - 1]);
                    t = fast_tanh(h);
                }
                myt = (lane == 31) ? t : myt;

                float w = 1.0f - myt;
                u.s.wring[s & 1][lane] = w;
                float c = 0.5f * ETA * w;
                uint32_t coff = (uint32_t)(s & 3) * 128u + (uint32_t)lane * 4u;
                u.s.cbuf[s & 3][lane] = c;
#pragma unroll
                for (int r = 0; r < NC - 1; r++) st_cluster_f32(cbr[r] + coff, c);
                __syncwarp();
                if (lane < NC) mbar_arrive_rel(cr_mine + (uint32_t)(s & 3) * 8u);
                if (lane == 0) mbar_arrive_local(cons_base + (uint32_t)(s & 1) * 8u);
                __syncwarp();
            }
        }
    } else if (wid <= 8) {
        // ---------------- worker warps 1..8 (all ranks) ----------------
        const int wwarp = wid - 1;
        const int widx = tid - 32;              // 0..255, owns th[widx]
        const uint32_t dst_base = mapa_rk(smem_u32(&u.s.dpart[0][rank][4 * wwarp]), 0);
        const uint32_t dr_base  = mapa_rk(smem_u32(&u.s.mbar_d[0]), 0);
        const uint32_t mc_base  = smem_u32(&u.s.mbar_c[0]);

        for (int t = 0; t < NBLK; t++) {
            if (t >= 3) {
                int uu = t - 3;
                mbar_wait(mc_base + (uint32_t)(uu & 3) * 8u, (uu >> 2) & 1);
                float tv = u.s.th[widx];
                const float* xp = xs + (size_t)uu * BLK * DDIM + colbase + widx;
                const float* cp = &u.s.cbuf[uu & 3][0];
#pragma unroll 8
                for (int j = 0; j < BLK; j++)
                    tv = fmaf(cp[j], xp[(size_t)j * DDIM], tv);
                u.s.th[widx] = tv;
            }
            asm volatile("bar.sync 1, 256;" ::: "memory");
            {   // matvec block t with current th (= A_{t-3})
                const float4* th4 = (const float4*)u.s.th;
                float4 t0 = th4[lane], t1 = th4[lane + 32];
                float sacc[4];
#pragma unroll
                for (int rr = 0; rr < 4; rr++) {
                    const float4* xr = (const float4*)(xs +
                        ((size_t)t * BLK + 4 * wwarp + rr) * DDIM + colbase);
                    float4 a = xr[lane], b = xr[lane + 32];
                    float p0 = a.x * t0.x; p0 = fmaf(a.y, t0.y, p0);
                    p0 = fmaf(a.z, t0.z, p0); p0 = fmaf(a.w, t0.w, p0);
                    float p1 = b.x * t1.x; p1 = fmaf(b.y, t1.y, p1);
                    p1 = fmaf(b.z, t1.z, p1); p1 = fmaf(b.w, t1.w, p1);
                    sacc[rr] = p0 + p1;
                }
#pragma unroll
                for (int rr = 0; rr < 4; rr++) {
                    sacc[rr] += __shfl_xor_sync(0xffffffffu, sacc[rr], 16);
                    sacc[rr] += __shfl_xor_sync(0xffffffffu, sacc[rr], 8);
                    sacc[rr] += __shfl_xor_sync(0xffffffffu, sacc[rr], 4);
                    sacc[rr] += __shfl_xor_sync(0xffffffffu, sacc[rr], 2);
                    sacc[rr] += __shfl_xor_sync(0xffffffffu, sacc[rr], 1);
                }
                if (lane == 0) {
                    uint32_t dst = dst_base + (uint32_t)(t & 3) * (NC * BLK * 4);
                    st_cluster_f32(dst + 0u,  0.5f * sacc[0]);
                    st_cluster_f32(dst + 4u,  0.5f * sacc[1]);
                    st_cluster_f32(dst + 8u,  0.5f * sacc[2]);
                    st_cluster_f32(dst + 12u, 0.5f * sacc[3]);
                    mbar_arrive_rel(dr_base + (uint32_t)(t & 3) * 8u);
                }
            }
            asm volatile("bar.sync 1, 256;" ::: "memory");
        }
        for (int t = NBLK; t < NBLK + 3; t++) {
            int uu = t - 3;
            mbar_wait(mc_base + (uint32_t)(uu & 3) * 8u, (uu >> 2) & 1);
            float tv = u.s.th[widx];
            const float* xp = xs + (size_t)uu * BLK * DDIM + colbase + widx;
            const float* cp = &u.s.cbuf[uu & 3][0];
#pragma unroll 8
            for (int j = 0; j < BLK; j++)
                tv = fmaf(cp[j], xp[(size_t)j * DDIM], tv);
            u.s.th[widx] = tv;
            asm volatile("bar.sync 1, 256;" ::: "memory");
        }
    } else {
        // ---------------- prefetch warp 9 (rank 0 only) ----------------
        if (rank == 0) {
            const int l9 = tid - 288;
            const uint32_t pf_base = smem_u32(&u.s.mbar_pf[0]);
            const uint32_t cons_base = smem_u32(&u.s.mbar_cons[0]);
            for (int s = 0; s < NBLK; s++) {
                if (l9 == 0) {
                    int f;
                    do { asm volatile("ld.acquire.gpu.global.b32 %0, [%1];"
                                      : "=r"(f) : "l"(&g_flag[s]) : "memory"); } while (!f);
                }
                __syncwarp();
                if (s >= 2)
                    mbar_wait(cons_base + (uint32_t)(s & 1) * 8u, ((s - 2) >> 1) & 1);
                const char* gs = (const char*)(g_WB + (size_t)s * BW * BLK);
                uint32_t gd = smem_u32(&u.s.Gsm[s & 1][0]);
#pragma unroll
                for (int i = 0; i < 24; i++)
                    cp_async16(gd + (uint32_t)(l9 + 32 * i) * 16u,
                               gs + (size_t)(l9 + 32 * i) * 16);
                cp_commit();
                cp_wait0();
                __syncwarp();
                if (l9 == 0) mbar_arrive_local(pf_base + (uint32_t)(s & 1) * 8u);
            }
        }
    }

    __syncthreads();
    for (int i = tid; i < SLICE; i += NTH) out[colbase + i] = u.s.th[i];
    cluster_sync_();
}

extern "C" void kernel_launch(void* const* d_in, const int* in_sizes, int n_in,
                              void* d_out, int out_size) {
    const float* theta = (const float*)d_in[0];
    const float* xs    = (const float*)d_in[1];
    if (in_sizes[0] != DDIM) {
        theta = (const float*)d_in[1];
        xs    = (const float*)d_in[0];
    }
    fused_kernel<<<NC + NBLK, NTH>>>(theta, xs, (float*)d_out);
}

// round 12
// speedup vs baseline: 1.4299x; 1.0493x over previous
#include <cuda_runtime.h>
#include <cstdint>

// Fused blocked online logistic-SGD scan.
// One kernel, 65 clusters x 8 CTAs:
//   cluster 0   : scan (chain warp + 8 worker warps/CTA + prefetch warp)
//   CTAs 8..519 : band-96 Gram for block m = bid-8, publish release-flag.
// g_WB[m][j][r] pre-scaled by ETA/4: j in [0,32): block m-2, [32,64): m-1,
//   [64,96): intra. Chain corrects dist-1/2 from its own w-history; workers run
//   theta lag-3. R12 (= R11 re-run, infra failure): workers pre-issue ALL x
//   loads (apply 32xLDG + matvec 8xLDG.128) into registers before the c-wait so
//   the mbarrier wait absorbs the memory latency -> worker tick issue-bound.

#define DDIM 2048
#define NSTEPS 16384
#define BLK 32
#define NBLK 512
#define ETA 0.01f
#define NC 8
#define SLICE 256
#define NTH 320
#define BW 96

__device__ float g_WB[(size_t)NBLK * BW * BLK];
__device__ int g_flag[NBLK];   // zero-init; set-once (idempotent across replays)

__device__ __forceinline__ float fast_tanh(float x) {
    float r; asm("tanh.approx.f32 %0, %1;" : "=f"(r) : "f"(x)); return r;
}
__device__ __forceinline__ uint32_t smem_u32(const void* p) {
    return (uint32_t)__cvta_generic_to_shared(p);
}
__device__ __forceinline__ uint32_t mapa_rk(uint32_t a, uint32_t rk) {
    uint32_t r; asm("mapa.shared::cluster.u32 %0, %1, %2;" : "=r"(r) : "r"(a), "r"(rk));
    return r;
}
__device__ __forceinline__ void st_cluster_f32(uint32_t a, float v) {
    asm volatile("st.shared::cluster.f32 [%0], %1;" :: "r"(a), "f"(v) : "memory");
}
__device__ __forceinline__ void cluster_sync_() {
    asm volatile("barrier.cluster.arrive.aligned;" ::: "memory");
    asm volatile("barrier.cluster.wait.aligned;" ::: "memory");
}
__device__ __forceinline__ void mbar_init(uint32_t a, uint32_t cnt) {
    asm volatile("mbarrier.init.shared.b64 [%0], %1;" :: "r"(a), "r"(cnt) : "memory");
}
__device__ __forceinline__ void mbar_arrive_rel(uint32_t a) {
    asm volatile("mbarrier.arrive.release.cluster.shared::cluster.b64 _, [%0];"
                 :: "r"(a) : "memory");
}
__device__ __forceinline__ void mbar_arrive_local(uint32_t a) {
    asm volatile("mbarrier.arrive.shared.b64 _, [%0];" :: "r"(a) : "memory");
}
__device__ __forceinline__ void mbar_wait(uint32_t a, int parity) {
    asm volatile(
        "{\n\t.reg .pred P;\n\t"
        "W_%=:\n\t"
        "mbarrier.try_wait.parity.acquire.cluster.shared::cta.b64 P, [%0], %1, 0x989680;\n\t"
        "@P bra.uni D_%=;\n\t"
        "bra.uni W_%=;\n\t"
        "D_%=:\n\t}"
        :: "r"(a), "r"(parity) : "memory");
}
__device__ __forceinline__ void cp_async16(uint32_t saddr, const void* gptr) {
    asm volatile("cp.async.cg.shared.global [%0], [%1], 16;"
                 :: "r"(saddr), "l"(gptr) : "memory");
}
__device__ __forceinline__ void cp_commit() { asm volatile("cp.async.commit_group;" ::: "memory"); }
__device__ __forceinline__ void cp_wait0()  { asm volatile("cp.async.wait_group 0;" ::: "memory"); }

struct ScanSh {
    float th[SLICE];
    float cbuf[4][BLK];
    float dpart[4][NC][BLK];
    float wring[2][BLK];
    unsigned long long mbar_d[4];    // 64 arrivals (8 warps x 8 CTAs)
    unsigned long long mbar_c[4];    // 1 arrival each
    unsigned long long mbar_pf[2];   // prefetch-done
    unsigned long long mbar_cons[2]; // chain-consumed
    alignas(16) float Gsm[2][BW * BLK];
};
struct GramSh { float Bs[96][65]; };
union Sh { ScanSh s; GramSh g; };

__global__ __launch_bounds__(NTH, 1) __cluster_dims__(NC, 1, 1)
void fused_kernel(const float* __restrict__ theta0, const float* __restrict__ xs,
                  float* __restrict__ out) {
    __shared__ Sh u;
    const int tid = threadIdx.x;
    const int bid = blockIdx.x;

    if (bid >= NC) {
        // ================= GRAM role: block m = bid - NC =================
        const int m = bid - NC;
        const int baserow = 32 * m - 64;
        const int r0 = (tid & 7) * 4, j0 = (tid >> 3) * 3;
        const bool act = (tid < 256);
        float acc[4][3];
#pragma unroll
        for (int a = 0; a < 4; a++)
#pragma unroll
            for (int b = 0; b < 3; b++) acc[a][b] = 0.f;

        for (int ch = 0; ch < DDIM / 64; ch++) {
#pragma unroll
            for (int q = 0; q < 5; q++) {
                int id = tid + NTH * q;
                if (id < 1536) {
                    int row = id >> 4, c4 = (id & 15) * 4;
                    int arow = baserow + row;
                    float4 v = make_float4(0.f, 0.f, 0.f, 0.f);
                    if (arow >= 0)
                        v = *(const float4*)(xs + (size_t)arow * DDIM + ch * 64 + c4);
                    u.g.Bs[row][c4+0]=v.x; u.g.Bs[row][c4+1]=v.y;
                    u.g.Bs[row][c4+2]=v.z; u.g.Bs[row][c4+3]=v.w;
                }
            }
            __syncthreads();
            if (act) {
#pragma unroll 8
                for (int d = 0; d < 64; d++) {
                    float a0=u.g.Bs[64+r0+0][d], a1=u.g.Bs[64+r0+1][d];
                    float a2=u.g.Bs[64+r0+2][d], a3=u.g.Bs[64+r0+3][d];
                    float b0=u.g.Bs[j0+0][d], b1=u.g.Bs[j0+1][d], b2=u.g.Bs[j0+2][d];
                    acc[0][0]=fmaf(a0,b0,acc[0][0]); acc[1][0]=fmaf(a1,b0,acc[1][0]);
                    acc[2][0]=fmaf(a2,b0,acc[2][0]); acc[3][0]=fmaf(a3,b0,acc[3][0]);
                    acc[0][1]=fmaf(a0,b1,acc[0][1]); acc[1][1]=fmaf(a1,b1,acc[1][1]);
                    acc[2][1]=fmaf(a2,b1,acc[2][1]); acc[3][1]=fmaf(a3,b1,acc[3][1]);
                    acc[0][2]=fmaf(a0,b2,acc[0][2]); acc[1][2]=fmaf(a1,b2,acc[1][2]);
                    acc[2][2]=fmaf(a2,b2,acc[2][2]); acc[3][2]=fmaf(a3,b2,acc[3][2]);
                }
            }
            __syncthreads();
        }
        if (act) {
            float* dst = g_WB + (size_t)m * (BW * BLK);
#pragma unroll
            for (int rr = 0; rr < 4; rr++)
#pragma unroll
                for (int jj = 0; jj < 3; jj++)
                    dst[(j0 + jj) * BLK + (r0 + rr)] = (0.25f * ETA) * acc[rr][jj];
        }
        __syncthreads();
        if (tid == 0) {
            __threadfence();
            *(volatile int*)&g_flag[m] = 1;
        }
        return;
    }

    // ===================== SCAN role: cluster 0 =====================
    uint32_t rank; asm("mov.u32 %0, %%cluster_ctarank;" : "=r"(rank));
    const int colbase = (int)rank * SLICE;
    const int wid = tid >> 5;
    const int lane = tid & 31;

    if (tid == 0) {
#pragma unroll
        for (int i = 0; i < 4; i++) {
            mbar_init(smem_u32(&u.s.mbar_d[i]), 8 * NC);
            mbar_init(smem_u32(&u.s.mbar_c[i]), 1);
        }
#pragma unroll
        for (int i = 0; i < 2; i++) {
            mbar_init(smem_u32(&u.s.mbar_pf[i]), 1);
            mbar_init(smem_u32(&u.s.mbar_cons[i]), 1);
        }
    }
    if (rank == 0 && tid < 64) ((float*)u.s.wring)[tid] = 0.f;
    for (int i = tid; i < SLICE; i += NTH) u.s.th[i] = theta0[colbase + i];
    __syncthreads();
    cluster_sync_();

    if (wid == 0) {
        // ---------------- chain warp (rank 0 only) ----------------
        if (rank == 0) {
            const uint32_t md_base = smem_u32(&u.s.mbar_d[0]);
            const uint32_t pf_base = smem_u32(&u.s.mbar_pf[0]);
            const uint32_t cons_base = smem_u32(&u.s.mbar_cons[0]);
            const uint32_t cb_base = smem_u32(&u.s.cbuf[0][0]);
            uint32_t cbr[NC - 1];
#pragma unroll
            for (int r = 1; r < NC; r++) cbr[r - 1] = mapa_rk(cb_base, (uint32_t)r);
            const uint32_t rkm = (lane < NC) ? (uint32_t)lane : 0u;
            const uint32_t cr_mine = mapa_rk(smem_u32(&u.s.mbar_c[0]), rkm);

            for (int s = 0; s < NBLK; s++) {
                mbar_wait(pf_base + (uint32_t)(s & 1) * 8u, (s >> 1) & 1);
                const float* Gb = &u.s.Gsm[s & 1][0];
                float Gd2[32], Gd1[32], Gi[32];
#pragma unroll
                for (int j = 0; j < 32; j++) Gd2[j] = Gb[j * 32 + lane];
#pragma unroll
                for (int j = 0; j < 32; j++) Gd1[j] = Gb[(32 + j) * 32 + lane];
#pragma unroll
                for (int j = 0; j < 32; j++) Gi[j]  = Gb[(64 + j) * 32 + lane];

                const float4* w2 = (const float4*)&u.s.wring[s & 1][0];
                const float4* w1 = (const float4*)&u.s.wring[(s + 1) & 1][0];
                float a0=0.f, a1=0.f, a2=0.f, a3=0.f;
#pragma unroll
                for (int i = 0; i < 8; i++) {
                    float4 q = w2[i];
                    a0 = fmaf(q.x, Gd2[4*i+0], a0); a1 = fmaf(q.y, Gd2[4*i+1], a1);
                    a2 = fmaf(q.z, Gd2[4*i+2], a2); a3 = fmaf(q.w, Gd2[4*i+3], a3);
                }
#pragma unroll
                for (int i = 0; i < 8; i++) {
                    float4 q = w1[i];
                    a0 = fmaf(q.x, Gd1[4*i+0], a0); a1 = fmaf(q.y, Gd1[4*i+1], a1);
                    a2 = fmaf(q.z, Gd1[4*i+2], a2); a3 = fmaf(q.w, Gd1[4*i+3], a3);
                }
                float corr = (a0 + a1) + (a2 + a3);

                mbar_wait(md_base + (uint32_t)(s & 3) * 8u, (s >> 2) & 1);
                const float* dp = &u.s.dpart[s & 3][0][0];
                float h = ((dp[lane] + dp[32 + lane]) + (dp[64 + lane] + dp[96 + lane]))
                        + ((dp[128 + lane] + dp[160 + lane]) + (dp[192 + lane] + dp[224 + lane]))
                        + corr;

                float t = fast_tanh(h);
                float myt = 0.f;
#pragma unroll
                for (int r = 1; r < 32; r++) {
                    float tb = __shfl_sync(0xffffffffu, t, r - 1);
                    myt = (lane == r - 1) ? t : myt;
                    h = fmaf(tb, -Gi[r - 1], h + Gi[r - 1]);
                    t = fast_tanh(h);
                }
                myt = (lane == 31) ? t : myt;

                float w = 1.0f - myt;
                u.s.wring[s & 1][lane] = w;
                float c = 0.5f * ETA * w;
                uint32_t coff = (uint32_t)(s & 3) * 128u + (uint32_t)lane * 4u;
                u.s.cbuf[s & 3][lane] = c;
#pragma unroll
                for (int r = 0; r < NC - 1; r++) st_cluster_f32(cbr[r] + coff, c);
                __syncwarp();
                if (lane < NC) mbar_arrive_rel(cr_mine + (uint32_t)(s & 3) * 8u);
                if (lane == 0) mbar_arrive_local(cons_base + (uint32_t)(s & 1) * 8u);
                __syncwarp();
            }
        }
    } else if (wid <= 8) {
        // ---------------- worker warps 1..8 (all ranks) ----------------
        const int wwarp = wid - 1;
        const int widx = tid - 32;              // 0..255, owns th[widx]
        const uint32_t dst_base = mapa_rk(smem_u32(&u.s.dpart[0][rank][4 * wwarp]), 0);
        const uint32_t dr_base  = mapa_rk(smem_u32(&u.s.mbar_d[0]), 0);
        const uint32_t mc_base  = smem_u32(&u.s.mbar_c[0]);

        for (int t = 0; t < NBLK; t++) {
            // -- pre-issue ALL x loads for this tick (before any wait) --
            // apply x column: block uu = t-3 (clamped to 0 for warm-up ticks;
            // values unused when t < 3, so the clamp only keeps addresses valid
            // and the load batch branch-free / front-scheduled).
            const int uu = t - 3;
            const int uuc = (uu >= 0) ? uu : 0;
            float apv[BLK];
            {
                const float* xp = xs + (size_t)uuc * BLK * DDIM + colbase + widx;
#pragma unroll
                for (int j = 0; j < BLK; j++) apv[j] = xp[(size_t)j * DDIM];
            }
            float4 mva[4], mvb[4];                // matvec x rows (block t)
#pragma unroll
            for (int rr = 0; rr < 4; rr++) {
                const float4* xr = (const float4*)(xs +
                    ((size_t)t * BLK + 4 * wwarp + rr) * DDIM + colbase);
                mva[rr] = xr[lane];
                mvb[rr] = xr[lane + 32];
            }

            if (t >= 3) {
                mbar_wait(mc_base + (uint32_t)(uu & 3) * 8u, (uu >> 2) & 1);
                float tv = u.s.th[widx];
                const float* cp = &u.s.cbuf[uu & 3][0];
#pragma unroll
                for (int j = 0; j < BLK; j++)
                    tv = fmaf(cp[j], apv[j], tv);
                u.s.th[widx] = tv;
            }
            asm volatile("bar.sync 1, 256;" ::: "memory");
            {   // matvec block t with current th (= A_{t-3})
                const float4* th4 = (const float4*)u.s.th;
                float4 t0 = th4[lane], t1 = th4[lane + 32];
                float sacc[4];
#pragma unroll
                for (int rr = 0; rr < 4; rr++) {
                    float4 a = mva[rr], b = mvb[rr];
                    float p0 = a.x * t0.x; p0 = fmaf(a.y, t0.y, p0);
                    p0 = fmaf(a.z, t0.z, p0); p0 = fmaf(a.w, t0.w, p0);
                    float p1 = b.x * t1.x; p1 = fmaf(b.y, t1.y, p1);
                    p1 = fmaf(b.z, t1.z, p1); p1 = fmaf(b.w, t1.w, p1);
                    sacc[rr] = p0 + p1;
                }
#pragma unroll
                for (int rr = 0; rr < 4; rr++) {
                    sacc[rr] += __shfl_xor_sync(0xffffffffu, sacc[rr], 16);
                    sacc[rr] += __shfl_xor_sync(0xffffffffu, sacc[rr], 8);
                    sacc[rr] += __shfl_xor_sync(0xffffffffu, sacc[rr], 4);
                    sacc[rr] += __shfl_xor_sync(0xffffffffu, sacc[rr], 2);
                    sacc[rr] += __shfl_xor_sync(0xffffffffu, sacc[rr], 1);
                }
                if (lane == 0) {
                    uint32_t dst = dst_base + (uint32_t)(t & 3) * (NC * BLK * 4);
                    st_cluster_f32(dst + 0u,  0.5f * sacc[0]);
                    st_cluster_f32(dst + 4u,  0.5f * sacc[1]);
                    st_cluster_f32(dst + 8u,  0.5f * sacc[2]);
                    st_cluster_f32(dst + 12u, 0.5f * sacc[3]);
                    mbar_arrive_rel(dr_base + (uint32_t)(t & 3) * 8u);
                }
            }
            asm volatile("bar.sync 1, 256;" ::: "memory");
        }
        for (int t = NBLK; t < NBLK + 3; t++) {
            int uu = t - 3;
            float apv[BLK];
            const float* xp = xs + (size_t)uu * BLK * DDIM + colbase + widx;
#pragma unroll
            for (int j = 0; j < BLK; j++) apv[j] = xp[(size_t)j * DDIM];
            mbar_wait(mc_base + (uint32_t)(uu & 3) * 8u, (uu >> 2) & 1);
            float tv = u.s.th[widx];
            const float* cp = &u.s.cbuf[uu & 3][0];
#pragma unroll
            for (int j = 0; j < BLK; j++)
                tv = fmaf(cp[j], apv[j], tv);
            u.s.th[widx] = tv;
            asm volatile("bar.sync 1, 256;" ::: "memory");
        }
    } else {
        // ---------------- prefetch warp 9 (rank 0 only) ----------------
        if (rank == 0) {
            const int l9 = tid - 288;
            const uint32_t pf_base = smem_u32(&u.s.mbar_pf[0]);
            const uint32_t cons_base = smem_u32(&u.s.mbar_cons[0]);
            for (int s = 0; s < NBLK; s++) {
                if (l9 == 0) {
                    int f;
                    do { asm volatile("ld.acquire.gpu.global.b32 %0, [%1];"
                                      : "=r"(f) : "l"(&g_flag[s]) : "memory"); } while (!f);
                }
                __syncwarp();
                if (s >= 2)
                    mbar_wait(cons_base + (uint32_t)(s & 1) * 8u, ((s - 2) >> 1) & 1);
                const char* gs = (const char*)(g_WB + (size_t)s * BW * BLK);
                uint32_t gd = smem_u32(&u.s.Gsm[s & 1][0]);
#pragma unroll
                for (int i = 0; i < 24; i++)
                    cp_async16(gd + (uint32_t)(l9 + 32 * i) * 16u,
                               gs + (size_t)(l9 + 32 * i) * 16);
                cp_commit();
                cp_wait0();
                __syncwarp();
                if (l9 == 0) mbar_arrive_local(pf_base + (uint32_t)(s & 1) * 8u);
            }
        }
    }

    __syncthreads();
    for (int i = tid; i < SLICE; i += NTH) out[colbase + i] = u.s.th[i];
    cluster_sync_();
}

extern "C" void kernel_launch(void* const* d_in, const int* in_sizes, int n_in,
                              void* d_out, int out_size) {
    const float* theta = (const float*)d_in[0];
    const float* xs    = (const float*)d_in[1];
    if (in_sizes[0] != DDIM) {
        theta = (const float*)d_in[1];
        xs    = (const float*)d_in[0];
    }
    fused_kernel<<<NC + NBLK, NTH>>>(theta, xs, (float*)d_out);
}

// round 14
// speedup vs baseline: 1.5463x; 1.0814x over previous
#include <cuda_runtime.h>
#include <cstdint>

// Fused blocked online logistic-SGD scan.
// One kernel, 65 clusters x 8 CTAs:
//   cluster 0   : scan (workers wid0-7, prefetch wid8, chain wid9)
//   CTAs 8..519 : band-96 Gram for block m = bid-8, publish release-flag.
// g_WB[m][j][r] pre-scaled by ETA/4: j in [0,32): block m-2, [32,64): m-1,
//   [64,96): intra. Chain corrects dist-1/2 from its own w-history; workers run
//   theta lag-3 with all x loads pre-issued before the c-wait.
// R14 (= R13 re-run, infra failure):
//   (a) per-CTA d aggregation -- worker warp0 gathers the CTA's 32 row
//   partials locally and does ONE remote store + ONE arrive (mbar_d 64->8
//   arrivals, killing ~1.9K cyc of smem-atomic arrival serialization);
//   (b) chain warp moved to wid9 (hi-wid-first arbiter priority).

#define DDIM 2048
#define NSTEPS 16384
#define BLK 32
#define NBLK 512
#define ETA 0.01f
#define NC 8
#define SLICE 256
#define NTH 320
#define BW 96

__device__ float g_WB[(size_t)NBLK * BW * BLK];
__device__ int g_flag[NBLK];   // zero-init; set-once (idempotent across replays)

__device__ __forceinline__ float fast_tanh(float x) {
    float r; asm("tanh.approx.f32 %0, %1;" : "=f"(r) : "f"(x)); return r;
}
__device__ __forceinline__ uint32_t smem_u32(const void* p) {
    return (uint32_t)__cvta_generic_to_shared(p);
}
__device__ __forceinline__ uint32_t mapa_rk(uint32_t a, uint32_t rk) {
    uint32_t r; asm("mapa.shared::cluster.u32 %0, %1, %2;" : "=r"(r) : "r"(a), "r"(rk));
    return r;
}
__device__ __forceinline__ void st_cluster_f32(uint32_t a, float v) {
    asm volatile("st.shared::cluster.f32 [%0], %1;" :: "r"(a), "f"(v) : "memory");
}
__device__ __forceinline__ void cluster_sync_() {
    asm volatile("barrier.cluster.arrive.aligned;" ::: "memory");
    asm volatile("barrier.cluster.wait.aligned;" ::: "memory");
}
__device__ __forceinline__ void mbar_init(uint32_t a, uint32_t cnt) {
    asm volatile("mbarrier.init.shared.b64 [%0], %1;" :: "r"(a), "r"(cnt) : "memory");
}
__device__ __forceinline__ void mbar_arrive_rel(uint32_t a) {
    asm volatile("mbarrier.arrive.release.cluster.shared::cluster.b64 _, [%0];"
                 :: "r"(a) : "memory");
}
__device__ __forceinline__ void mbar_arrive_local(uint32_t a) {
    asm volatile("mbarrier.arrive.shared.b64 _, [%0];" :: "r"(a) : "memory");
}
__device__ __forceinline__ void mbar_wait(uint32_t a, int parity) {
    asm volatile(
        "{\n\t.reg .pred P;\n\t"
        "W_%=:\n\t"
        "mbarrier.try_wait.parity.acquire.cluster.shared::cta.b64 P, [%0], %1, 0x989680;\n\t"
        "@P bra.uni D_%=;\n\t"
        "bra.uni W_%=;\n\t"
        "D_%=:\n\t}"
        :: "r"(a), "r"(parity) : "memory");
}
__device__ __forceinline__ void cp_async16(uint32_t saddr, const void* gptr) {
    asm volatile("cp.async.cg.shared.global [%0], [%1], 16;"
                 :: "r"(saddr), "l"(gptr) : "memory");
}
__device__ __forceinline__ void cp_commit() { asm volatile("cp.async.commit_group;" ::: "memory"); }
__device__ __forceinline__ void cp_wait0()  { asm volatile("cp.async.wait_group 0;" ::: "memory"); }

struct ScanSh {
    float th[SLICE];
    float cbuf[4][BLK];
    float dpart[4][NC][BLK];   // CTA0 only: aggregated per-CTA partials
    float dloc[4][BLK];        // per-CTA local row partials (8 warps x 4 rows)
    float wring[2][BLK];
    unsigned long long mbar_d[4];    // CTA0: NC arrivals (1 per CTA)
    unsigned long long mbar_c[4];    // per CTA: 1 arrival each
    unsigned long long mbar_pf[2];   // prefetch-done
    unsigned long long mbar_cons[2]; // chain-consumed
    alignas(16) float Gsm[2][BW * BLK];
};
struct GramSh { float Bs[96][65]; };
union Sh { ScanSh s; GramSh g; };

__global__ __launch_bounds__(NTH, 1) __cluster_dims__(NC, 1, 1)
void fused_kernel(const float* __restrict__ theta0, const float* __restrict__ xs,
                  float* __restrict__ out) {
    __shared__ Sh u;
    const int tid = threadIdx.x;
    const int bid = blockIdx.x;

    if (bid >= NC) {
        // ================= GRAM role: block m = bid - NC =================
        const int m = bid - NC;
        const int baserow = 32 * m - 64;
        const int r0 = (tid & 7) * 4, j0 = (tid >> 3) * 3;
        const bool act = (tid < 256);
        float acc[4][3];
#pragma unroll
        for (int a = 0; a < 4; a++)
#pragma unroll
            for (int b = 0; b < 3; b++) acc[a][b] = 0.f;

        for (int ch = 0; ch < DDIM / 64; ch++) {
#pragma unroll
            for (int q = 0; q < 5; q++) {
                int id = tid + NTH * q;
                if (id < 1536) {
                    int row = id >> 4, c4 = (id & 15) * 4;
                    int arow = baserow + row;
                    float4 v = make_float4(0.f, 0.f, 0.f, 0.f);
                    if (arow >= 0)
                        v = *(const float4*)(xs + (size_t)arow * DDIM + ch * 64 + c4);
                    u.g.Bs[row][c4+0]=v.x; u.g.Bs[row][c4+1]=v.y;
                    u.g.Bs[row][c4+2]=v.z; u.g.Bs[row][c4+3]=v.w;
                }
            }
            __syncthreads();
            if (act) {
#pragma unroll 8
                for (int d = 0; d < 64; d++) {
                    float a0=u.g.Bs[64+r0+0][d], a1=u.g.Bs[64+r0+1][d];
                    float a2=u.g.Bs[64+r0+2][d], a3=u.g.Bs[64+r0+3][d];
                    float b0=u.g.Bs[j0+0][d], b1=u.g.Bs[j0+1][d], b2=u.g.Bs[j0+2][d];
                    acc[0][0]=fmaf(a0,b0,acc[0][0]); acc[1][0]=fmaf(a1,b0,acc[1][0]);
                    acc[2][0]=fmaf(a2,b0,acc[2][0]); acc[3][0]=fmaf(a3,b0,acc[3][0]);
                    acc[0][1]=fmaf(a0,b1,acc[0][1]); acc[1][1]=fmaf(a1,b1,acc[1][1]);
                    acc[2][1]=fmaf(a2,b1,acc[2][1]); acc[3][1]=fmaf(a3,b1,acc[3][1]);
                    acc[0][2]=fmaf(a0,b2,acc[0][2]); acc[1][2]=fmaf(a1,b2,acc[1][2]);
                    acc[2][2]=fmaf(a2,b2,acc[2][2]); acc[3][2]=fmaf(a3,b2,acc[3][2]);
                }
            }
            __syncthreads();
        }
        if (act) {
            float* dst = g_WB + (size_t)m * (BW * BLK);
#pragma unroll
            for (int rr = 0; rr < 4; rr++)
#pragma unroll
                for (int jj = 0; jj < 3; jj++)
                    dst[(j0 + jj) * BLK + (r0 + rr)] = (0.25f * ETA) * acc[rr][jj];
        }
        __syncthreads();
        if (tid == 0) {
            __threadfence();
            *(volatile int*)&g_flag[m] = 1;
        }
        return;
    }

    // ===================== SCAN role: cluster 0 =====================
    uint32_t rank; asm("mov.u32 %0, %%cluster_ctarank;" : "=r"(rank));
    const int colbase = (int)rank * SLICE;
    const int wid = tid >> 5;
    const int lane = tid & 31;

    if (tid == 0) {
#pragma unroll
        for (int i = 0; i < 4; i++) {
            mbar_init(smem_u32(&u.s.mbar_d[i]), NC);   // 1 arrival per CTA
            mbar_init(smem_u32(&u.s.mbar_c[i]), 1);
        }
#pragma unroll
        for (int i = 0; i < 2; i++) {
            mbar_init(smem_u32(&u.s.mbar_pf[i]), 1);
            mbar_init(smem_u32(&u.s.mbar_cons[i]), 1);
        }
    }
    if (rank == 0 && tid < 64) ((float*)u.s.wring)[tid] = 0.f;
    for (int i = tid; i < SLICE; i += NTH) u.s.th[i] = theta0[colbase + i];
    __syncthreads();
    cluster_sync_();

    if (wid < 8) {
        // ---------------- worker warps 0..7 (all ranks) ----------------
        const int wwarp = wid;
        const int widx = tid;                   // 0..255, owns th[widx]
        const uint32_t dst_base = mapa_rk(smem_u32(&u.s.dpart[0][rank][0]), 0);
        const uint32_t dr_base  = mapa_rk(smem_u32(&u.s.mbar_d[0]), 0);
        const uint32_t mc_base  = smem_u32(&u.s.mbar_c[0]);

        for (int t = 0; t < NBLK; t++) {
            // -- pre-issue ALL x loads for this tick (before any wait) --
            const int uu = t - 3;
            const int uuc = (uu >= 0) ? uu : 0;
            float apv[BLK];
            {
                const float* xp = xs + (size_t)uuc * BLK * DDIM + colbase + widx;
#pragma unroll
                for (int j = 0; j < BLK; j++) apv[j] = xp[(size_t)j * DDIM];
            }
            float4 mva[4], mvb[4];                // matvec x rows (block t)
#pragma unroll
            for (int rr = 0; rr < 4; rr++) {
                const float4* xr = (const float4*)(xs +
                    ((size_t)t * BLK + 4 * wwarp + rr) * DDIM + colbase);
                mva[rr] = xr[lane];
                mvb[rr] = xr[lane + 32];
            }

            if (t >= 3) {
                mbar_wait(mc_base + (uint32_t)(uu & 3) * 8u, (uu >> 2) & 1);
                float tv = u.s.th[widx];
                const float* cp = &u.s.cbuf[uu & 3][0];
#pragma unroll
                for (int j = 0; j < BLK; j++)
                    tv = fmaf(cp[j], apv[j], tv);
                u.s.th[widx] = tv;
            }
            asm volatile("bar.sync 1, 256;" ::: "memory");
            {   // matvec block t with current th (= A_{t-3})
                const float4* th4 = (const float4*)u.s.th;
                float4 t0 = th4[lane], t1 = th4[lane + 32];
                float sacc[4];
#pragma unroll
                for (int rr = 0; rr < 4; rr++) {
                    float4 a = mva[rr], b = mvb[rr];
                    float p0 = a.x * t0.x; p0 = fmaf(a.y, t0.y, p0);
                    p0 = fmaf(a.z, t0.z, p0); p0 = fmaf(a.w, t0.w, p0);
                    float p1 = b.x * t1.x; p1 = fmaf(b.y, t1.y, p1);
                    p1 = fmaf(b.z, t1.z, p1); p1 = fmaf(b.w, t1.w, p1);
                    sacc[rr] = p0 + p1;
                }
#pragma unroll
                for (int rr = 0; rr < 4; rr++) {
                    sacc[rr] += __shfl_xor_sync(0xffffffffu, sacc[rr], 16);
                    sacc[rr] += __shfl_xor_sync(0xffffffffu, sacc[rr], 8);
                    sacc[rr] += __shfl_xor_sync(0xffffffffu, sacc[rr], 4);
                    sacc[rr] += __shfl_xor_sync(0xffffffffu, sacc[rr], 2);
                    sacc[rr] += __shfl_xor_sync(0xffffffffu, sacc[rr], 1);
                }
                // lane 0: store this warp's 4 row-partials to LOCAL smem
                if (lane == 0) {
                    float* dl = &u.s.dloc[t & 3][4 * wwarp];
                    dl[0] = 0.5f * sacc[0];
                    dl[1] = 0.5f * sacc[1];
                    dl[2] = 0.5f * sacc[2];
                    dl[3] = 0.5f * sacc[3];
                }
            }
            asm volatile("bar.sync 1, 256;" ::: "memory");
            // warp 0 aggregates: ONE remote 128B store + ONE arrive per CTA
            if (wwarp == 0) {
                float v = u.s.dloc[t & 3][lane];
                st_cluster_f32(dst_base + (uint32_t)(t & 3) * (NC * BLK * 4)
                               + (uint32_t)lane * 4u, v);
                __syncwarp();
                if (lane == 0)
                    mbar_arrive_rel(dr_base + (uint32_t)(t & 3) * 8u);
            }
        }
        for (int t = NBLK; t < NBLK + 3; t++) {
            int uu = t - 3;
            float apv[BLK];
            const float* xp = xs + (size_t)uu * BLK * DDIM + colbase + widx;
#pragma unroll
            for (int j = 0; j < BLK; j++) apv[j] = xp[(size_t)j * DDIM];
            mbar_wait(mc_base + (uint32_t)(uu & 3) * 8u, (uu >> 2) & 1);
            float tv = u.s.th[widx];
            const float* cp = &u.s.cbuf[uu & 3][0];
#pragma unroll
            for (int j = 0; j < BLK; j++)
                tv = fmaf(cp[j], apv[j], tv);
            u.s.th[widx] = tv;
            asm volatile("bar.sync 1, 256;" ::: "memory");
        }
    } else if (wid == 8) {
        // ---------------- prefetch warp (rank 0 only) ----------------
        if (rank == 0) {
            const int l9 = lane;
            const uint32_t pf_base = smem_u32(&u.s.mbar_pf[0]);
            const uint32_t cons_base = smem_u32(&u.s.mbar_cons[0]);
            for (int s = 0; s < NBLK; s++) {
                if (l9 == 0) {
                    int f;
                    do { asm volatile("ld.acquire.gpu.global.b32 %0, [%1];"
                                      : "=r"(f) : "l"(&g_flag[s]) : "memory"); } while (!f);
                }
                __syncwarp();
                if (s >= 2)
                    mbar_wait(cons_base + (uint32_t)(s & 1) * 8u, ((s - 2) >> 1) & 1);
                const char* gs = (const char*)(g_WB + (size_t)s * BW * BLK);
                uint32_t gd = smem_u32(&u.s.Gsm[s & 1][0]);
#pragma unroll
                for (int i = 0; i < 24; i++)
                    cp_async16(gd + (uint32_t)(l9 + 32 * i) * 16u,
                               gs + (size_t)(l9 + 32 * i) * 16);
                cp_commit();
                cp_wait0();
                __syncwarp();
                if (l9 == 0) mbar_arrive_local(pf_base + (uint32_t)(s & 1) * 8u);
            }
        }
    } else {
        // ---------------- chain warp wid 9 (rank 0 only; hi-wid priority) ----
        if (rank == 0) {
            const uint32_t md_base = smem_u32(&u.s.mbar_d[0]);
            const uint32_t pf_base = smem_u32(&u.s.mbar_pf[0]);
            const uint32_t cons_base = smem_u32(&u.s.mbar_cons[0]);
            const uint32_t cb_base = smem_u32(&u.s.cbuf[0][0]);
            uint32_t cbr[NC - 1];
#pragma unroll
            for (int r = 1; r < NC; r++) cbr[r - 1] = mapa_rk(cb_base, (uint32_t)r);
            const uint32_t rkm = (lane < NC) ? (uint32_t)lane : 0u;
            const uint32_t cr_mine = mapa_rk(smem_u32(&u.s.mbar_c[0]), rkm);

            for (int s = 0; s < NBLK; s++) {
                mbar_wait(pf_base + (uint32_t)(s & 1) * 8u, (s >> 1) & 1);
                const float* Gb = &u.s.Gsm[s & 1][0];
                float Gd2[32], Gd1[32], Gi[32];
#pragma unroll
                for (int j = 0; j < 32; j++) Gd2[j] = Gb[j * 32 + lane];
#pragma unroll
                for (int j = 0; j < 32; j++) Gd1[j] = Gb[(32 + j) * 32 + lane];
#pragma unroll
                for (int j = 0; j < 32; j++) Gi[j]  = Gb[(64 + j) * 32 + lane];

                const float4* w2 = (const float4*)&u.s.wring[s & 1][0];
                const float4* w1 = (const float4*)&u.s.wring[(s + 1) & 1][0];
                float a0=0.f, a1=0.f, a2=0.f, a3=0.f;
#pragma unroll
                for (int i = 0; i < 8; i++) {
                    float4 q = w2[i];
                    a0 = fmaf(q.x, Gd2[4*i+0], a0); a1 = fmaf(q.y, Gd2[4*i+1], a1);
                    a2 = fmaf(q.z, Gd2[4*i+2], a2); a3 = fmaf(q.w, Gd2[4*i+3], a3);
                }
#pragma unroll
                for (int i = 0; i < 8; i++) {
                    float4 q = w1[i];
                    a0 = fmaf(q.x, Gd1[4*i+0], a0); a1 = fmaf(q.y, Gd1[4*i+1], a1);
                    a2 = fmaf(q.z, Gd1[4*i+2], a2); a3 = fmaf(q.w, Gd1[4*i+3], a3);
                }
                float corr = (a0 + a1) + (a2 + a3);

                mbar_wait(md_base + (uint32_t)(s & 3) * 8u, (s >> 2) & 1);
                const float* dp = &u.s.dpart[s & 3][0][0];
                float h = ((dp[lane] + dp[32 + lane]) + (dp[64 + lane] + dp[96 + lane]))
                        + ((dp[128 + lane] + dp[160 + lane]) + (dp[192 + lane] + dp[224 + lane]))
                        + corr;

                float t = fast_tanh(h);
                float myt = 0.f;
#pragma unroll
                for (int r = 1; r < 32; r++) {
                    float tb = __shfl_sync(0xffffffffu, t, r - 1);
                    myt = (lane == r - 1) ? t : myt;
                    h = fmaf(tb, -Gi[r - 1], h + Gi[r - 1]);
                    t = fast_tanh(h);
                }
                myt = (lane == 31) ? t : myt;

                float w = 1.0f - myt;
                u.s.wring[s & 1][lane] = w;
                float c = 0.5f * ETA * w;
                uint32_t coff = (uint32_t)(s & 3) * 128u + (uint32_t)lane * 4u;
                u.s.cbuf[s & 3][lane] = c;
#pragma unroll
                for (int r = 0; r < NC - 1; r++) st_cluster_f32(cbr[r] + coff, c);
                __syncwarp();
                if (lane < NC) mbar_arrive_rel(cr_mine + (uint32_t)(s & 3) * 8u);
                if (lane == 0) mbar_arrive_local(cons_base + (uint32_t)(s & 1) * 8u);
                __syncwarp();
            }
        }
    }

    __syncthreads();
    for (int i = tid; i < SLICE; i += NTH) out[colbase + i] = u.s.th[i];
    cluster_sync_();
}

extern "C" void kernel_launch(void* const* d_in, const int* in_sizes, int n_in,
                              void* d_out, int out_size) {
    const float* theta = (const float*)d_in[0];
    const float* xs    = (const float*)d_in[1];
    if (in_sizes[0] != DDIM) {
        theta = (const float*)d_in[1];
        xs    = (const float*)d_in[0];
    }
    fused_kernel<<<NC + NBLK, NTH>>>(theta, xs, (float*)d_out);
}